// round 5
// baseline (speedup 1.0000x reference)
#include <cuda_runtime.h>
#include <math.h>

// Problem constants
#define Bc   4
#define Sc   1024
#define HIDc 1024
#define Hc   16
#define Dc   64

// Scratch for Q, K, V in [B,H,S,D] layout (16 MB each)
__device__ float g_q[Bc * Hc * Sc * Dc];
__device__ float g_k[Bc * Hc * Sc * Dc];
__device__ float g_v[Bc * Hc * Sc * Dc];

// ---------------------------------------------------------------------------
// f32x2 packed helpers
// ---------------------------------------------------------------------------
typedef unsigned long long ull;

__device__ __forceinline__ ull pk2(float lo, float hi) {
    ull r;
    asm("mov.b64 %0, {%1, %2};" : "=l"(r) : "f"(lo), "f"(hi));
    return r;
}
__device__ __forceinline__ void upk2(float& lo, float& hi, ull v) {
    asm("mov.b64 {%0, %1}, %2;" : "=f"(lo), "=f"(hi) : "l"(v));
}
__device__ __forceinline__ void fma2(ull& d, ull a, ull b) {
    asm("fma.rn.f32x2 %0, %1, %2, %0;" : "+l"(d) : "l"(a), "l"(b));
}

// ---------------------------------------------------------------------------
// Kernel A: projection GEMM  C = X @ W + bias, scattered to [B,H,S,D]
// (unchanged from R3 — f32x2 inner loop)
// ---------------------------------------------------------------------------
__global__ __launch_bounds__(256) void gemm_proj(const float* __restrict__ X,
                                                 const float* __restrict__ W,
                                                 const float* __restrict__ bias,
                                                 int which)
{
    __shared__ float As[16][132];   // transposed A tile: As[k][m]
    __shared__ float Bs[16][132];   // Bs[k][n]
    float* outp = (which == 0) ? g_q : (which == 1) ? g_k : g_v;

    const int tid = threadIdx.x;
    const int m0  = blockIdx.y * 128;
    const int n0  = blockIdx.x * 128;
    const int ty  = tid >> 4;     // 0..15
    const int tx  = tid & 15;     // 0..15

    ull acc2[4][8];
#pragma unroll
    for (int i = 0; i < 4; i++)
#pragma unroll
        for (int j = 0; j < 8; j++) acc2[i][j] = 0ull;

    for (int k0 = 0; k0 < 1024; k0 += 16) {
#pragma unroll
        for (int i = 0; i < 2; i++) {
            int f   = tid + i * 256;
            int row = f >> 2;
            int kc  = (f & 3) << 2;
            float4 va = *(const float4*)(X + (size_t)(m0 + row) * 1024 + k0 + kc);
            As[kc + 0][row] = va.x;
            As[kc + 1][row] = va.y;
            As[kc + 2][row] = va.z;
            As[kc + 3][row] = va.w;
        }
#pragma unroll
        for (int i = 0; i < 2; i++) {
            int f  = tid + i * 256;
            int kr = f >> 5;
            int nc = (f & 31) << 2;
            *(float4*)&Bs[kr][nc] =
                *(const float4*)(W + (size_t)(k0 + kr) * 1024 + n0 + nc);
        }
        __syncthreads();

#pragma unroll
        for (int kk = 0; kk < 16; kk++) {
            ull a2[4];
#pragma unroll
            for (int i2 = 0; i2 < 4; i2++)
                a2[i2] = *(const ull*)&As[kk][ty * 8 + i2 * 2];
            float bn[8];
            *(float4*)&bn[0] = *(const float4*)&Bs[kk][tx * 8];
            *(float4*)&bn[4] = *(const float4*)&Bs[kk][tx * 8 + 4];
#pragma unroll
            for (int j = 0; j < 8; j++) {
                ull b2 = pk2(bn[j], bn[j]);
#pragma unroll
                for (int i2 = 0; i2 < 4; i2++)
                    fma2(acc2[i2][j], a2[i2], b2);
            }
        }
        __syncthreads();
    }

#pragma unroll
    for (int i2 = 0; i2 < 4; i2++) {
#pragma unroll
        for (int j = 0; j < 8; j++) {
            float lo, hi;
            upk2(lo, hi, acc2[i2][j]);
            int n = n0 + tx * 8 + j;
            int h = n >> 6;
            int d = n & 63;
            {
                int m = m0 + ty * 8 + i2 * 2;
                int b = m >> 10, s = m & 1023;
                outp[(((size_t)(b * Hc + h)) * Sc + s) * Dc + d] = lo + bias[n];
            }
            {
                int m = m0 + ty * 8 + i2 * 2 + 1;
                int b = m >> 10, s = m & 1023;
                outp[(((size_t)(b * Hc + h)) * Sc + s) * Dc + d] = hi + bias[n];
            }
        }
    }
}

// ---------------------------------------------------------------------------
// Kernel B: fused attention. 128-query x 64-key tiles, 512 threads (16 warps),
// 4x4 micro-tile, f32x2 d-packed score FMAs, swizzled K/E rows,
// duplicated P pairs for packed PV.
// ---------------------------------------------------------------------------
#define QS 68     // Q row stride (floats)
#define KS 82     // K row stride (+ per-row swizzle)
#define ES 82     // E row stride (+ per-row swizzle)
#define VS 68     // V row stride
#define PS 130    // P row stride (64 dup-pairs + pad)

#define QOFF  0                    // 128 x 68        = 8704
#define KOFF  8704                 // 64 x 82 + 16    = 5264
#define VOFF  13968                // 64 x 68         = 4352
#define EOFF  18320                // 191 x 82 + 16   = 15680
#define POFF  34000                // 128 x 130       = 16640
#define DNOFF 50640                // 128
#define AMOFF 50768                // 64
#define SKOFF 50832                // 64
#define SMEMF 50896
#define ATTN_SMEM_BYTES (SMEMF * 4)   // 203584 B

__global__ __launch_bounds__(512, 1) void attn_kernel(const float* __restrict__ attn_mask,
                                                      const int*   __restrict__ skim,
                                                      const float* __restrict__ dist_emb,
                                                      float*       __restrict__ out)
{
    extern __shared__ float smf[];
    const int tid = threadIdx.x;
    const int l0  = blockIdx.x * 128;
    const int bh  = blockIdx.y;
    const int b   = bh >> 4;
    const int h   = bh & 15;
    const int ty  = tid >> 4;   // 0..31 -> 4 query rows each
    const int tx  = tid & 15;   // 0..15 -> 4 key cols each

    const float* q = g_q + (size_t)bh * Sc * Dc;
    const float* k = g_k + (size_t)bh * Sc * Dc;
    const float* v = g_v + (size_t)bh * Sc * Dc;

    // Load Q tile (128x64), stride 68 (16B-aligned rows)
#pragma unroll
    for (int i = 0; i < 4; i++) {
        int f   = tid + i * 512;       // 0..2047 float4s
        int row = f >> 4;
        int c4  = (f & 15) << 2;
        float4 val = *(const float4*)(q + (size_t)(l0 + row) * 64 + c4);
        *(float4*)&smf[QOFF + row * QS + c4] = val;
    }
    if (tid < 128) smf[DNOFF + tid] = 0.f;

    ull pv2[4][2];                 // PV acc: pairs along d (dd, dd+1)
#pragma unroll
    for (int i = 0; i < 4; i++) { pv2[i][0] = 0ull; pv2[i][1] = 0ull; }

    const int jb0 = 4 * (ty - tx) + 60;          // first diag row, in [0,184]
    int sw[2];
#pragma unroll
    for (int g = 0; g < 2; g++) sw[g] = ((((jb0 >> 2) + g) & 7) << 1);
    const int ebr = EOFF + jb0 * ES;
    const int qb  = QOFF + ty * 4 * QS;
    const int kb  = KOFF + tx * 4 * KS + ((tx & 7) << 1);

    for (int r0 = 0; r0 < Sc; r0 += 64) {
        __syncthreads();   // prior PV done before tiles are overwritten

        // K (swizzled rows) and V: 64 rows x 16 float4 each
#pragma unroll
        for (int i = 0; i < 2; i++) {
            int f   = tid + i * 512;
            int row = f >> 4;
            int c4  = (f & 15) << 2;
            float4 kv = *(const float4*)(k + (size_t)(r0 + row) * 64 + c4);
            int ka = KOFF + row * KS + (((row >> 2) & 7) << 1) + c4;
            *(float2*)&smf[ka]     = make_float2(kv.x, kv.y);
            *(float2*)&smf[ka + 2] = make_float2(kv.z, kv.w);
            float4 vv = *(const float4*)(v + (size_t)(r0 + row) * 64 + c4);
            *(float4*)&smf[VOFF + row * VS + c4] = vv;
        }
        // E band: rows [l0-r0+960 .. +1150], 191 rows x 64 (swizzled)
        {
            int ebase = l0 - r0 + 960;
#pragma unroll
            for (int i = 0; i < 6; i++) {
                int f = tid + i * 512;
                if (f < 3056) {
                    int row = f >> 4;
                    int c4  = (f & 15) << 2;
                    float4 ev = *(const float4*)(dist_emb + (size_t)(ebase + row) * 64 + c4);
                    int ea = EOFF + row * ES + (((row >> 2) & 7) << 1) + c4;
                    *(float2*)&smf[ea]     = make_float2(ev.x, ev.y);
                    *(float2*)&smf[ea + 2] = make_float2(ev.z, ev.w);
                }
            }
        }
        if (tid < 64) {
            smf[AMOFF + tid] = attn_mask[b * Sc + r0 + tid];
            smf[SKOFF + tid] = (float)skim[b * Sc + r0 + tid];
        }
        __syncthreads();

        // ---- Scores: s[il][ir] = sum_d q*k + sum_d q*e, f32x2 over d-pairs
        ull s2[4][4];
#pragma unroll
        for (int i = 0; i < 4; i++)
#pragma unroll
            for (int j = 0; j < 4; j++) s2[i][j] = 0ull;

#pragma unroll 4
        for (int d2 = 0; d2 < 32; d2++) {
            const int d = d2 << 1;
            ull q2[4], k2[4], e2[7];
#pragma unroll
            for (int il = 0; il < 4; il++)
                q2[il] = *(const ull*)&smf[qb + il * QS + d];
#pragma unroll
            for (int ir = 0; ir < 4; ir++)
                k2[ir] = *(const ull*)&smf[kb + ir * KS + d];
#pragma unroll
            for (int t = 0; t < 7; t++)
                e2[t] = *(const ull*)&smf[ebr + t * ES + sw[t >> 2] + d];
#pragma unroll
            for (int il = 0; il < 4; il++)
#pragma unroll
                for (int ir = 0; ir < 4; ir++) {
                    fma2(s2[il][ir], q2[il], k2[ir]);
                    fma2(s2[il][ir], q2[il], e2[il - ir + 3]);
                }
        }

        // ---- probs: exp(s/8 + am) * skim; write duplicated pairs; denoms
#pragma unroll
        for (int il = 0; il < 4; il++) {
            int l = ty * 4 + il;
            float rs = 0.f;
#pragma unroll
            for (int ir = 0; ir < 4; ir++) {
                float lo, hi;
                upk2(lo, hi, s2[il][ir]);
                float p = __expf((lo + hi) * 0.125f + smf[AMOFF + tx * 4 + ir])
                          * smf[SKOFF + tx * 4 + ir];
                *(ull*)&smf[POFF + l * PS + (tx * 4 + ir) * 2] = pk2(p, p);
                rs += p;
            }
            rs += __shfl_xor_sync(0xffffffffu, rs, 1);
            rs += __shfl_xor_sync(0xffffffffu, rs, 2);
            rs += __shfl_xor_sync(0xffffffffu, rs, 4);
            rs += __shfl_xor_sync(0xffffffffu, rs, 8);
            if (tx == 0) smf[DNOFF + l] += rs;
        }
        __syncwarp();   // P rows for this thread's ty written by its 16-lane half

        // ---- PV: pv2[il][dd2] += P_dup * (v[dd], v[dd+1])
#pragma unroll 4
        for (int rr = 0; rr < 64; rr++) {
            ull v0 = *(const ull*)&smf[VOFF + rr * VS + tx * 4];
            ull v1 = *(const ull*)&smf[VOFF + rr * VS + tx * 4 + 2];
#pragma unroll
            for (int il = 0; il < 4; il++) {
                ull p2 = *(const ull*)&smf[POFF + (ty * 4 + il) * PS + rr * 2];
                fma2(pv2[il][0], p2, v0);
                fma2(pv2[il][1], p2, v1);
            }
        }
    }
    __syncwarp();

    // ---- write out: out[b, l, h*64 + d] = acc / (eps + denom)
#pragma unroll
    for (int il = 0; il < 4; il++) {
        int l = l0 + ty * 4 + il;
        float dinv = 1.f / (1e-8f + smf[DNOFF + ty * 4 + il]);
        float a0, a1, a2_, a3;
        upk2(a0, a1, pv2[il][0]);
        upk2(a2_, a3, pv2[il][1]);
        float4 o = make_float4(a0 * dinv, a1 * dinv, a2_ * dinv, a3 * dinv);
        *(float4*)&out[((size_t)(b * Sc + l)) * HIDc + h * 64 + tx * 4] = o;
    }
}

// ---------------------------------------------------------------------------
extern "C" void kernel_launch(void* const* d_in, const int* in_sizes, int n_in,
                              void* d_out, int out_size)
{
    const float* hidden = (const float*)d_in[0];
    const float* amask  = (const float*)d_in[1];
    const int*   skim   = (const int*)  d_in[2];
    const float* Wq     = (const float*)d_in[3];
    const float* bq     = (const float*)d_in[4];
    const float* Wk     = (const float*)d_in[5];
    const float* bk     = (const float*)d_in[6];
    const float* Wv     = (const float*)d_in[7];
    const float* bv     = (const float*)d_in[8];
    const float* demb   = (const float*)d_in[9];
    float* out = (float*)d_out;

    dim3 ggrid(8, 32);   // N/128, M/128
    gemm_proj<<<ggrid, 256>>>(hidden, Wq, bq, 0);
    gemm_proj<<<ggrid, 256>>>(hidden, Wk, bk, 1);
    gemm_proj<<<ggrid, 256>>>(hidden, Wv, bv, 2);

    cudaFuncSetAttribute(attn_kernel,
                         cudaFuncAttributeMaxDynamicSharedMemorySize,
                         ATTN_SMEM_BYTES);
    dim3 agrid(Sc / 128, Bc * Hc);
    attn_kernel<<<agrid, 512, ATTN_SMEM_BYTES>>>(amask, skim, demb, out);
}